// round 8
// baseline (speedup 1.0000x reference)
#include <cuda_runtime.h>
#include <cuda_fp16.h>
#include <cstdint>

// ---------------------------------------------------------------------------
// Problem constants
// ---------------------------------------------------------------------------
#define OC      8192
#define IC      8192
#define BATCH   64
#define PROWS   4096      // packed rows (OC/2)
#define KSPLIT  4

// ---- GEMM config (mma.sync m16n8k16 fp16, plain sm_103) ----
#define TILE_P     64                 // packed rows per CTA -> 128 oc
#define KEXT       (IC / KSPLIT)      // 2048 per CTA
#define KC         128                // k per chunk
#define NCH        (KEXT / KC)        // 16 chunks
#define SA_STRIDE  136                // ints per A row (128 + 8 pad; %32=8 -> conflict-free)
#define SB_STRIDE  136                // fp16 per B row (128 + 8 pad)
#define STAGE_A_BYTES (TILE_P * SA_STRIDE * 4)          // 34816
#define STAGE_B_BYTES (BATCH * SB_STRIDE * 2)           // 17408
#define STAGE_BYTES   (STAGE_A_BYTES + STAGE_B_BYTES)   // 52224
#define SMEM_TOTAL    (2 * STAGE_BYTES)                 // 104448 -> occ 2 = 209KB/SM

// ---------------------------------------------------------------------------
// Scratch (device globals; allocation-free contract)
// ---------------------------------------------------------------------------
__device__ __half g_xh[BATCH * IC];                    // fp16 activations [64][8192]
__device__ float  g_Spart[256];                        // row-sum partials [64 b][4 chunks]
__device__ float  g_partial[KSPLIT * BATCH * OC];      // [4][64][8192]

// ---------------------------------------------------------------------------
// Helpers
// ---------------------------------------------------------------------------
__device__ __forceinline__ uint32_t smem_u32(const void* p) {
    uint32_t a;
    asm("{ .reg .u64 t; cvta.to.shared.u64 t, %1; cvt.u32.u64 %0, t; }" : "=r"(a) : "l"(p));
    return a;
}

__device__ __forceinline__ void cp16(uint32_t dst, const void* src) {
    asm volatile("cp.async.cg.shared.global [%0], [%1], 16;" :: "r"(dst), "l"(src));
}
#define CP_COMMIT() asm volatile("cp.async.commit_group;" ::: "memory")
#define CP_WAIT1()  asm volatile("cp.async.wait_group 1;" ::: "memory")

__device__ __forceinline__ void mma16816(float* c, const uint32_t* a, const uint32_t* b) {
    asm volatile("mma.sync.aligned.m16n8k16.row.col.f32.f16.f16.f32 "
                 "{%0,%1,%2,%3}, {%4,%5,%6,%7}, {%8,%9}, {%0,%1,%2,%3};"
                 : "+f"(c[0]), "+f"(c[1]), "+f"(c[2]), "+f"(c[3])
                 : "r"(a[0]), "r"(a[1]), "r"(a[2]), "r"(a[3]), "r"(b[0]), "r"(b[1]));
}

__device__ __forceinline__ void ldsm4(uint32_t& r0, uint32_t& r1, uint32_t& r2,
                                      uint32_t& r3, uint32_t addr) {
    asm volatile("ldmatrix.sync.aligned.m8n8.x4.shared.b16 {%0,%1,%2,%3}, [%4];"
                 : "=r"(r0), "=r"(r1), "=r"(r2), "=r"(r3) : "r"(addr));
}

// ---------------------------------------------------------------------------
// Kernel 1: x -> fp16 (2x float4 per thread), partial row sums OF THE ROUNDED
// VALUES (so the +64 dequant offset cancels exactly). 256 CTAs.
// ---------------------------------------------------------------------------
__global__ void prep_kernel(const float* __restrict__ x) {
    __shared__ float red[8];
    const int b  = blockIdx.x >> 2;
    const int c0 = (blockIdx.x & 3) * 2048 + threadIdx.x * 4;
    float s = 0.f;
    #pragma unroll
    for (int half = 0; half < 2; ++half) {
        const int c = c0 + half * 1024;
        const float4 v = *(const float4*)(x + b * IC + c);
        const __half h0 = __float2half(v.x), h1 = __float2half(v.y);
        const __half h2 = __float2half(v.z), h3 = __float2half(v.w);
        __half2 p0 = __halves2half2(h0, h1), p1 = __halves2half2(h2, h3);
        uint2 st;
        st.x = *(uint32_t*)&p0; st.y = *(uint32_t*)&p1;
        *(uint2*)(g_xh + b * IC + c) = st;
        s += (__half2float(h0) + __half2float(h1))
           + (__half2float(h2) + __half2float(h3));
    }
    #pragma unroll
    for (int o = 16; o > 0; o >>= 1)
        s += __shfl_xor_sync(0xFFFFFFFFu, s, o);
    if ((threadIdx.x & 31) == 0) red[threadIdx.x >> 5] = s;
    __syncthreads();
    if (threadIdx.x == 0) {
        float t = 0.f;
        #pragma unroll
        for (int j = 0; j < 8; ++j) t += red[j];
        g_Spart[blockIdx.x] = t;
    }
}

// ---------------------------------------------------------------------------
// Kernel 2: fused int4-dequant + fp16 mma.sync GEMM
//   grid (64, 4). Warp (wr 0..3, wc 0..1): wr owns 16 packed rows, extracts
//   BOTH nibbles from one int2 load; wc owns 32 batch. B fragments loaded via
//   ldmatrix.x4 (2 per kk). KC=128, 2-stage cp.async, occ 2.
//   Dequant: fp16 bits 0x5400|(q<<4) == 64+q exactly; offset cancels via S.
// ---------------------------------------------------------------------------
__global__ void __launch_bounds__(256, 2)
gemm_kernel(const int* __restrict__ packed) {
    extern __shared__ char smem[];
    const uint32_t smem_b32 = smem_u32(smem);
    const int tid  = threadIdx.x;
    const int wid  = tid >> 5, lane = tid & 31;
    const int g    = lane >> 2, t = lane & 3;
    const int wr   = wid & 3,  wc = wid >> 2;
    const int p0   = blockIdx.x * TILE_P;
    const int ks   = blockIdx.y;
    const int k0   = ks * KEXT;

    // ldmatrix per-lane byte offsets within the B stage (2 x4 ops per kk):
    //   x4 #m: tiles j=0..3 -> (nf = 2m + (j>>1), kh = j&1); lane: j=lane>>3, row=lane&7
    const int ld_j   = lane >> 3;
    const int ld_row = lane & 7;
    uint32_t b_off[2];
    #pragma unroll
    for (int m = 0; m < 2; ++m) {
        const int nf = 2 * m + (ld_j >> 1);
        const int kh = ld_j & 1;
        b_off[m] = (uint32_t)(((wc * 32 + nf * 8 + ld_row) * SB_STRIDE + kh * 8) * 2);
    }

    float accL[4][4], accH[4][4];
    #pragma unroll
    for (int j = 0; j < 4; ++j)
        #pragma unroll
        for (int q = 0; q < 4; ++q) { accL[j][q] = 0.f; accH[j][q] = 0.f; }

    auto issue = [&](int c) {
        const int s = c & 1;
        const int kc = k0 + c * KC;
        const uint32_t sa = smem_b32 + s * STAGE_BYTES;
        const uint32_t sb = sa + STAGE_A_BYTES;
        #pragma unroll
        for (int j = 0; j < 8; ++j) {               // A: 64 rows x 512B
            const int i = tid + j * 256;
            const int r = i >> 5, si = i & 31;
            cp16(sa + (uint32_t)(r * SA_STRIDE + si * 4) * 4,
                 packed + (long)(p0 + r) * IC + kc + si * 4);
        }
        #pragma unroll
        for (int j = 0; j < 4; ++j) {               // B: 64 rows x 256B
            const int i = tid + j * 256;
            const int r = i >> 4, si = i & 15;
            cp16(sb + (uint32_t)(r * SB_STRIDE + si * 8) * 2,
                 g_xh + (long)r * IC + kc + si * 8);
        }
        CP_COMMIT();
    };

    issue(0);
    for (int c = 0; c < NCH; ++c) {
        if (c + 1 < NCH) issue(c + 1);
        else CP_COMMIT();                 // keep group count uniform
        CP_WAIT1();                       // chunk c resident
        __syncthreads();

        const char* A = smem + (c & 1) * STAGE_BYTES;
        const uint32_t sb32 = smem_b32 + (c & 1) * STAGE_BYTES + STAGE_A_BYTES;

        #pragma unroll
        for (int kk = 0; kk < 8; ++kk) {
            // --- A fragments: one int2 per (kh,hr), both nibbles extracted ---
            uint32_t afl[4], afh[4];
            #pragma unroll
            for (int kh = 0; kh < 2; ++kh) {
                #pragma unroll
                for (int hr = 0; hr < 2; ++hr) {
                    const int2 v = *(const int2*)(A + ((wr * 16 + g + hr * 8) * SA_STRIDE
                                                      + kk * 16 + 2 * t + kh * 8) * 4);
                    const int idx = hr + 2 * kh;
                    afl[idx] = (((uint32_t)v.x << 4) & 0xF0u)
                             | (((uint32_t)v.y << 20) & 0xF00000u) | 0x54005400u;
                    afh[idx] = ((uint32_t)v.x & 0xF0u)
                             | (((uint32_t)v.y << 16) & 0xF00000u) | 0x54005400u;
                }
            }
            // --- B fragments: 2 x ldmatrix.x4 covers nf=0..3, kh=0..1 ---
            uint32_t br[2][4];
            ldsm4(br[0][0], br[0][1], br[0][2], br[0][3], sb32 + b_off[0] + kk * 32);
            ldsm4(br[1][0], br[1][1], br[1][2], br[1][3], sb32 + b_off[1] + kk * 32);

            #pragma unroll
            for (int nf = 0; nf < 4; ++nf) {
                uint32_t bf[2];
                bf[0] = br[nf >> 1][(nf & 1) * 2];
                bf[1] = br[nf >> 1][(nf & 1) * 2 + 1];
                mma16816(accL[nf], afl, bf);
                mma16816(accH[nf], afh, bf);
            }
        }
        __syncthreads();
    }

    // ---- epilogue: transpose through smem, then coalesced float4 stores ----
    float* sm = (float*)smem;                  // [64 b][132] (pad 4) = 33792B
    #pragma unroll
    for (int nf = 0; nf < 4; ++nf)
        #pragma unroll
        for (int q = 0; q < 4; ++q) {
            const int mrow = wr * 16 + g + (q >> 1) * 8;              // 0..63
            const int b    = wc * 32 + nf * 8 + 2 * t + (q & 1);      // 0..63
            sm[b * 132 + mrow]      = accL[nf][q];                    // low nibble
            sm[b * 132 + 64 + mrow] = accH[nf][q];                    // high nibble
        }
    __syncthreads();
    #pragma unroll
    for (int j = 0; j < 8; ++j) {
        const int i = tid + j * 256;           // 2048 float4
        const int b  = i >> 5;
        const int mv = (i & 31) * 4;
        const float4 v = *(const float4*)(sm + b * 132 + mv);
        const long oc = (mv < 64) ? (long)(p0 + mv) : (long)(PROWS + p0 + mv - 64);
        *(float4*)(g_partial + (((long)(ks * BATCH + b)) << 13) + oc) = v;
    }
}

// ---------------------------------------------------------------------------
// Kernel 3: sum k-splits + affine epilogue (vectorized float4 over oc)
//   out[b,oc] = delta[oc] * (dot' - (zp[oc]+64)*S_h[b]) + bias[oc]
// ---------------------------------------------------------------------------
__global__ void reduce_kernel(const float* __restrict__ delta,
                              const float* __restrict__ zp,
                              const float* __restrict__ bias,
                              float* __restrict__ out) {
    const int idx4 = (blockIdx.x * 256 + threadIdx.x) * 4;  // b*8192 + oc
    const int b  = idx4 >> 13;
    const int oc = idx4 & (OC - 1);
    float4 dot = make_float4(0.f, 0.f, 0.f, 0.f);
    #pragma unroll
    for (int s = 0; s < KSPLIT; ++s) {
        const float4 p = *(const float4*)(g_partial + (long)(s * BATCH + b) * OC + oc);
        dot.x += p.x; dot.y += p.y; dot.z += p.z; dot.w += p.w;
    }
    float S = 0.f;
    #pragma unroll
    for (int j = 0; j < 4; ++j) S += g_Spart[b * 4 + j];
    const float4 d  = *(const float4*)(delta + oc);
    const float4 z  = *(const float4*)(zp + oc);
    const float4 bi = *(const float4*)(bias + oc);
    float4 o;
    o.x = d.x * (dot.x - (z.x + 64.f) * S) + bi.x;
    o.y = d.y * (dot.y - (z.y + 64.f) * S) + bi.y;
    o.z = d.z * (dot.z - (z.z + 64.f) * S) + bi.z;
    o.w = d.w * (dot.w - (z.w + 64.f) * S) + bi.w;
    *(float4*)(out + idx4) = o;
}

// ---------------------------------------------------------------------------
// Launch
// ---------------------------------------------------------------------------
extern "C" void kernel_launch(void* const* d_in, const int* in_sizes, int n_in,
                              void* d_out, int out_size) {
    const float* x      = (const float*)d_in[0];
    const int*   packed = (const int*)d_in[1];
    const float* delta  = (const float*)d_in[2];
    const float* zp     = (const float*)d_in[3];
    const float* bias   = (const float*)d_in[4];
    float* out = (float*)d_out;

    cudaFuncSetAttribute(gemm_kernel, cudaFuncAttributeMaxDynamicSharedMemorySize, SMEM_TOTAL);

    prep_kernel<<<256, 256>>>(x);
    gemm_kernel<<<dim3(64, KSPLIT), 256, SMEM_TOTAL>>>(packed);
    reduce_kernel<<<(BATCH * OC) / 1024, 256>>>(delta, zp, bias, out);
}

// round 10
// speedup vs baseline: 1.4662x; 1.4662x over previous
#include <cuda_runtime.h>
#include <cuda_fp16.h>
#include <cstdint>

// ---------------------------------------------------------------------------
// Problem constants
// ---------------------------------------------------------------------------
#define OC      8192
#define IC      8192
#define BATCH   64
#define PROWS   4096      // packed rows (OC/2)
#define KSPLIT  4

// ---- GEMM config (mma.sync m16n8k16 fp16, plain sm_103) ----
#define TILE_P     64                 // packed rows per CTA -> 128 oc
#define KEXT       (IC / KSPLIT)      // 2048 per CTA
#define KC         128                // k per chunk
#define NCH        (KEXT / KC)        // 16 chunks
#define SA_STRIDE  136                // ints per A row (128 + 8 pad; %32=8 -> conflict-free)
#define SB_STRIDE  136                // fp16 per B row (128 + 8 pad)
#define STAGE_A_BYTES (TILE_P * SA_STRIDE * 4)          // 34816
#define STAGE_B_BYTES (BATCH * SB_STRIDE * 2)           // 17408
#define STAGE_BYTES   (STAGE_A_BYTES + STAGE_B_BYTES)   // 52224
#define SMEM_TOTAL    (2 * STAGE_BYTES)                 // 104448 -> occ 2 = 209KB/SM

// ---------------------------------------------------------------------------
// Scratch (device globals; allocation-free contract)
// ---------------------------------------------------------------------------
__device__ __half g_xh[BATCH * IC];                    // fp16 activations [64][8192]
__device__ float  g_Spart[512];                        // row-sum partials [64 b][8 chunks]
__device__ float  g_partial[KSPLIT * BATCH * OC];      // [4][64][8192]

// ---------------------------------------------------------------------------
// Helpers
// ---------------------------------------------------------------------------
__device__ __forceinline__ uint32_t smem_u32(const void* p) {
    uint32_t a;
    asm("{ .reg .u64 t; cvta.to.shared.u64 t, %1; cvt.u32.u64 %0, t; }" : "=r"(a) : "l"(p));
    return a;
}

__device__ __forceinline__ void cp16(uint32_t dst, const void* src) {
    asm volatile("cp.async.cg.shared.global [%0], [%1], 16;" :: "r"(dst), "l"(src));
}
#define CP_COMMIT() asm volatile("cp.async.commit_group;" ::: "memory")
#define CP_WAIT1()  asm volatile("cp.async.wait_group 1;" ::: "memory")

__device__ __forceinline__ void mma16816(float* c, const uint32_t* a, const uint32_t* b) {
    asm volatile("mma.sync.aligned.m16n8k16.row.col.f32.f16.f16.f32 "
                 "{%0,%1,%2,%3}, {%4,%5,%6,%7}, {%8,%9}, {%0,%1,%2,%3};"
                 : "+f"(c[0]), "+f"(c[1]), "+f"(c[2]), "+f"(c[3])
                 : "r"(a[0]), "r"(a[1]), "r"(a[2]), "r"(a[3]), "r"(b[0]), "r"(b[1]));
}

// ---------------------------------------------------------------------------
// Kernel 1: x -> fp16 (vectorized), partial row sums OF THE ROUNDED VALUES
// (so the +64 dequant offset cancels exactly in the reduce). 512 CTAs.
// ---------------------------------------------------------------------------
__global__ void prep_kernel(const float* __restrict__ x) {
    __shared__ float red[8];
    const int b  = blockIdx.x >> 3;
    const int c0 = (blockIdx.x & 7) * 1024 + threadIdx.x * 4;
    const float4 v = *(const float4*)(x + b * IC + c0);
    const __half h0 = __float2half(v.x), h1 = __float2half(v.y);
    const __half h2 = __float2half(v.z), h3 = __float2half(v.w);
    __half2 p0 = __halves2half2(h0, h1), p1 = __halves2half2(h2, h3);
    uint2 st;
    st.x = *(uint32_t*)&p0; st.y = *(uint32_t*)&p1;
    *(uint2*)(g_xh + b * IC + c0) = st;
    float s = (__half2float(h0) + __half2float(h1))
            + (__half2float(h2) + __half2float(h3));
    #pragma unroll
    for (int o = 16; o > 0; o >>= 1)
        s += __shfl_xor_sync(0xFFFFFFFFu, s, o);
    if ((threadIdx.x & 31) == 0) red[threadIdx.x >> 5] = s;
    __syncthreads();
    if (threadIdx.x == 0) {
        float t = 0.f;
        #pragma unroll
        for (int j = 0; j < 8; ++j) t += red[j];
        g_Spart[blockIdx.x] = t;
    }
}

// ---------------------------------------------------------------------------
// Kernel 2: fused int4-dequant + fp16 mma.sync GEMM (R7-proven structure)
//   grid (64, 4). Warp (wr 0..3, wc 0..1): wr owns 16 packed rows, extracts
//   BOTH nibbles from one int2 load; wc owns 32 batch. Conflict-free strides,
//   KC=128 (16 chunks), 2-stage cp.async, two syncs per chunk (safe).
//   Dequant: fp16 bits 0x5400|(q<<4) == 64+q exactly; offset cancels via S.
// ---------------------------------------------------------------------------
__global__ void __launch_bounds__(256, 2)
gemm_kernel(const int* __restrict__ packed) {
    extern __shared__ char smem[];
    const uint32_t smem_b32 = smem_u32(smem);
    const int tid  = threadIdx.x;
    const int wid  = tid >> 5, lane = tid & 31;
    const int g    = lane >> 2, t = lane & 3;
    const int wr   = wid & 3,  wc = wid >> 2;
    const int p0   = blockIdx.x * TILE_P;
    const int ks   = blockIdx.y;
    const int k0   = ks * KEXT;

    float accL[4][4], accH[4][4];
    #pragma unroll
    for (int j = 0; j < 4; ++j)
        #pragma unroll
        for (int q = 0; q < 4; ++q) { accL[j][q] = 0.f; accH[j][q] = 0.f; }

    auto issue = [&](int c) {
        const int s = c & 1;
        const int kc = k0 + c * KC;
        const uint32_t sa = smem_b32 + s * STAGE_BYTES;
        const uint32_t sb = sa + STAGE_A_BYTES;
        #pragma unroll
        for (int j = 0; j < 8; ++j) {               // A: 64 rows x 512B
            const int i = tid + j * 256;
            const int r = i >> 5, si = i & 31;
            cp16(sa + (uint32_t)(r * SA_STRIDE + si * 4) * 4,
                 packed + (long)(p0 + r) * IC + kc + si * 4);
        }
        #pragma unroll
        for (int j = 0; j < 4; ++j) {               // B: 64 rows x 256B
            const int i = tid + j * 256;
            const int r = i >> 4, si = i & 15;
            cp16(sb + (uint32_t)(r * SB_STRIDE + si * 8) * 2,
                 g_xh + (long)r * IC + kc + si * 8);
        }
        CP_COMMIT();
    };

    issue(0);
    for (int c = 0; c < NCH; ++c) {
        if (c + 1 < NCH) issue(c + 1);
        else CP_COMMIT();                 // keep group count uniform
        CP_WAIT1();                       // chunk c resident
        __syncthreads();

        const char* A = smem + (c & 1) * STAGE_BYTES;
        const char* B = A + STAGE_A_BYTES;

        #pragma unroll
        for (int kk = 0; kk < 8; ++kk) {
            uint32_t afl[4], afh[4];
            #pragma unroll
            for (int kh = 0; kh < 2; ++kh) {
                #pragma unroll
                for (int hr = 0; hr < 2; ++hr) {
                    const int2 v = *(const int2*)(A + ((wr * 16 + g + hr * 8) * SA_STRIDE
                                                      + kk * 16 + 2 * t + kh * 8) * 4);
                    const int idx = hr + 2 * kh;
                    afl[idx] = (((uint32_t)v.x << 4) & 0xF0u)
                             | (((uint32_t)v.y << 20) & 0xF00000u) | 0x54005400u;
                    afh[idx] = ((uint32_t)v.x & 0xF0u)
                             | (((uint32_t)v.y << 16) & 0xF00000u) | 0x54005400u;
                }
            }
            #pragma unroll
            for (int nf = 0; nf < 4; ++nf) {
                const int n = wc * 32 + nf * 8 + g;
                uint32_t bf[2];
                bf[0] = *(const uint32_t*)(B + (n * SB_STRIDE + kk * 16 + 2 * t) * 2);
                bf[1] = *(const uint32_t*)(B + (n * SB_STRIDE + kk * 16 + 2 * t + 8) * 2);
                mma16816(accL[nf], afl, bf);
                mma16816(accH[nf], afh, bf);
            }
        }
        __syncthreads();
    }

    // ---- epilogue: transpose through smem, then coalesced float4 stores ----
    float* sm = (float*)smem;                  // [64 b][132] (pad 4) = 33792B
    #pragma unroll
    for (int nf = 0; nf < 4; ++nf)
        #pragma unroll
        for (int q = 0; q < 4; ++q) {
            const int mrow = wr * 16 + g + (q >> 1) * 8;              // 0..63
            const int b    = wc * 32 + nf * 8 + 2 * t + (q & 1);      // 0..63
            sm[b * 132 + mrow]      = accL[nf][q];                    // low nibble
            sm[b * 132 + 64 + mrow] = accH[nf][q];                    // high nibble
        }
    __syncthreads();
    #pragma unroll
    for (int j = 0; j < 8; ++j) {
        const int i = tid + j * 256;           // 2048 float4
        const int b  = i >> 5;
        const int mv = (i & 31) * 4;
        const float4 v = *(const float4*)(sm + b * 132 + mv);
        const long oc = (mv < 64) ? (long)(p0 + mv) : (long)(PROWS + p0 + mv - 64);
        *(float4*)(g_partial + (((long)(ks * BATCH + b)) << 13) + oc) = v;
    }
}

// ---------------------------------------------------------------------------
// Kernel 3: sum k-splits + affine epilogue (vectorized float4 over oc)
//   out[b,oc] = delta[oc] * (dot' - (zp[oc]+64)*S_h[b]) + bias[oc]
// ---------------------------------------------------------------------------
__global__ void reduce_kernel(const float* __restrict__ delta,
                              const float* __restrict__ zp,
                              const float* __restrict__ bias,
                              float* __restrict__ out) {
    const int idx4 = (blockIdx.x * 256 + threadIdx.x) * 4;  // b*8192 + oc
    const int b  = idx4 >> 13;
    const int oc = idx4 & (OC - 1);
    float4 dot = make_float4(0.f, 0.f, 0.f, 0.f);
    #pragma unroll
    for (int s = 0; s < KSPLIT; ++s) {
        const float4 p = *(const float4*)(g_partial + (long)(s * BATCH + b) * OC + oc);
        dot.x += p.x; dot.y += p.y; dot.z += p.z; dot.w += p.w;
    }
    float S = 0.f;
    #pragma unroll
    for (int j = 0; j < 8; ++j) S += g_Spart[b * 8 + j];
    const float4 d  = *(const float4*)(delta + oc);
    const float4 z  = *(const float4*)(zp + oc);
    const float4 bi = *(const float4*)(bias + oc);
    float4 o;
    o.x = d.x * (dot.x - (z.x + 64.f) * S) + bi.x;
    o.y = d.y * (dot.y - (z.y + 64.f) * S) + bi.y;
    o.z = d.z * (dot.z - (z.z + 64.f) * S) + bi.z;
    o.w = d.w * (dot.w - (z.w + 64.f) * S) + bi.w;
    *(float4*)(out + idx4) = o;
}

// ---------------------------------------------------------------------------
// Launch
// ---------------------------------------------------------------------------
extern "C" void kernel_launch(void* const* d_in, const int* in_sizes, int n_in,
                              void* d_out, int out_size) {
    const float* x      = (const float*)d_in[0];
    const int*   packed = (const int*)d_in[1];
    const float* delta  = (const float*)d_in[2];
    const float* zp     = (const float*)d_in[3];
    const float* bias   = (const float*)d_in[4];
    float* out = (float*)d_out;

    cudaFuncSetAttribute(gemm_kernel, cudaFuncAttributeMaxDynamicSharedMemorySize, SMEM_TOTAL);

    prep_kernel<<<512, 256>>>(x);
    gemm_kernel<<<dim3(64, KSPLIT), 256, SMEM_TOTAL>>>(packed);
    reduce_kernel<<<(BATCH * OC) / 1024, 256>>>(delta, zp, bias, out);
}

// round 11
// speedup vs baseline: 1.5293x; 1.0430x over previous
#include <cuda_runtime.h>
#include <cuda_fp16.h>
#include <cstdint>

// ---------------------------------------------------------------------------
// Problem constants
// ---------------------------------------------------------------------------
#define OC      8192
#define IC      8192
#define BATCH   64
#define PROWS   4096      // packed rows (OC/2)
#define NSLOT   5         // max k-splits per tile (balanced 296-CTA grid)

// ---- GEMM config (mma.sync m16n8k16 fp16, plain sm_103) ----
#define TILE_P     64                 // packed rows per CTA -> 128 oc
#define KC         128                // k per chunk
#define SA_STRIDE  136                // ints per A row (128 + 8 pad; %32=8 -> conflict-free)
#define SB_STRIDE  136                // fp16 per B row (128 + 8 pad)
#define STAGE_A_BYTES (TILE_P * SA_STRIDE * 4)          // 34816
#define STAGE_B_BYTES (BATCH * SB_STRIDE * 2)           // 17408
#define STAGE_BYTES   (STAGE_A_BYTES + STAGE_B_BYTES)   // 52224
#define SMEM_TOTAL    (2 * STAGE_BYTES)                 // 104448 -> occ 2 = 209KB/SM

// ---------------------------------------------------------------------------
// Scratch (device globals; allocation-free contract)
// g_partial slot 4 is only written by 5-split tiles (0..39); for tiles 40..63
// it keeps its zero initialization -> deterministic, and reduce adds 0.
// ---------------------------------------------------------------------------
__device__ __half g_xh[BATCH * IC];                    // fp16 activations [64][8192]
__device__ float  g_Spart[512];                        // row-sum partials [64 b][8 chunks]
__device__ float  g_partial[NSLOT * BATCH * OC];       // [5][64][8192]

// ---------------------------------------------------------------------------
// Helpers
// ---------------------------------------------------------------------------
__device__ __forceinline__ uint32_t smem_u32(const void* p) {
    uint32_t a;
    asm("{ .reg .u64 t; cvta.to.shared.u64 t, %1; cvt.u32.u64 %0, t; }" : "=r"(a) : "l"(p));
    return a;
}

__device__ __forceinline__ void cp16(uint32_t dst, const void* src) {
    asm volatile("cp.async.cg.shared.global [%0], [%1], 16;" :: "r"(dst), "l"(src));
}
#define CP_COMMIT() asm volatile("cp.async.commit_group;" ::: "memory")
#define CP_WAIT1()  asm volatile("cp.async.wait_group 1;" ::: "memory")

__device__ __forceinline__ void mma16816(float* c, const uint32_t* a, const uint32_t* b) {
    asm volatile("mma.sync.aligned.m16n8k16.row.col.f32.f16.f16.f32 "
                 "{%0,%1,%2,%3}, {%4,%5,%6,%7}, {%8,%9}, {%0,%1,%2,%3};"
                 : "+f"(c[0]), "+f"(c[1]), "+f"(c[2]), "+f"(c[3])
                 : "r"(a[0]), "r"(a[1]), "r"(a[2]), "r"(a[3]), "r"(b[0]), "r"(b[1]));
}

// ---------------------------------------------------------------------------
// Kernel 1: x -> fp16 (vectorized), partial row sums OF THE ROUNDED VALUES
// (so the +64 dequant offset cancels exactly in the reduce). 512 CTAs.
// ---------------------------------------------------------------------------
__global__ void prep_kernel(const float* __restrict__ x) {
    __shared__ float red[8];
    const int b  = blockIdx.x >> 3;
    const int c0 = (blockIdx.x & 7) * 1024 + threadIdx.x * 4;
    const float4 v = *(const float4*)(x + b * IC + c0);
    const __half h0 = __float2half(v.x), h1 = __float2half(v.y);
    const __half h2 = __float2half(v.z), h3 = __float2half(v.w);
    __half2 p0 = __halves2half2(h0, h1), p1 = __halves2half2(h2, h3);
    uint2 st;
    st.x = *(uint32_t*)&p0; st.y = *(uint32_t*)&p1;
    *(uint2*)(g_xh + b * IC + c0) = st;
    float s = (__half2float(h0) + __half2float(h1))
            + (__half2float(h2) + __half2float(h3));
    #pragma unroll
    for (int o = 16; o > 0; o >>= 1)
        s += __shfl_xor_sync(0xFFFFFFFFu, s, o);
    if ((threadIdx.x & 31) == 0) red[threadIdx.x >> 5] = s;
    __syncthreads();
    if (threadIdx.x == 0) {
        float t = 0.f;
        #pragma unroll
        for (int j = 0; j < 8; ++j) t += red[j];
        g_Spart[blockIdx.x] = t;
    }
}

// ---------------------------------------------------------------------------
// Kernel 2: fused int4-dequant + fp16 mma.sync GEMM (R7 inner loop, balanced
// 296-CTA grid = exactly 2 CTAs per SM via LUT[bid%148]).
//   Work decode: bids 0..199   -> tiles 0..39,  5 splits {13,13,13,13,12} chunks
//                bids 200..295 -> tiles 40..63, 4 splits {16,16,16,16}
//   Pairing (b, b+148) puts a 16-chunk heavy with a 13-chunk light:
//   max SM load 29 chunk-units vs 32 for the old 256-CTA grid.
//   Dequant: fp16 bits 0x5400|(q<<4) == 64+q exactly; offset cancels via S.
// ---------------------------------------------------------------------------
__global__ void __launch_bounds__(256, 2)
gemm_kernel(const int* __restrict__ packed) {
    extern __shared__ char smem[];
    const uint32_t smem_b32 = smem_u32(smem);
    const int tid  = threadIdx.x;
    const int wid  = tid >> 5, lane = tid & 31;
    const int g    = lane >> 2, t = lane & 3;
    const int wr   = wid & 3,  wc = wid >> 2;

    // ---- balanced work decode ----
    const int bid = blockIdx.x;
    int tile, slot, chunk0, nch;
    if (bid < 200) {
        tile   = bid / 5;
        slot   = bid - tile * 5;
        nch    = (slot < 4) ? 13 : 12;
        chunk0 = slot * 13;
    } else {
        const int b2 = bid - 200;
        tile   = 40 + (b2 >> 2);
        slot   = b2 & 3;
        nch    = 16;
        chunk0 = slot << 4;
    }
    const int p0 = tile * TILE_P;
    const int k0 = chunk0 * KC;

    float accL[4][4], accH[4][4];
    #pragma unroll
    for (int j = 0; j < 4; ++j)
        #pragma unroll
        for (int q = 0; q < 4; ++q) { accL[j][q] = 0.f; accH[j][q] = 0.f; }

    auto issue = [&](int c) {
        const int s = c & 1;
        const int kc = k0 + c * KC;
        const uint32_t sa = smem_b32 + s * STAGE_BYTES;
        const uint32_t sb = sa + STAGE_A_BYTES;
        #pragma unroll
        for (int j = 0; j < 8; ++j) {               // A: 64 rows x 512B
            const int i = tid + j * 256;
            const int r = i >> 5, si = i & 31;
            cp16(sa + (uint32_t)(r * SA_STRIDE + si * 4) * 4,
                 packed + (long)(p0 + r) * IC + kc + si * 4);
        }
        #pragma unroll
        for (int j = 0; j < 4; ++j) {               // B: 64 rows x 256B
            const int i = tid + j * 256;
            const int r = i >> 4, si = i & 15;
            cp16(sb + (uint32_t)(r * SB_STRIDE + si * 8) * 2,
                 g_xh + (long)r * IC + kc + si * 8);
        }
        CP_COMMIT();
    };

    issue(0);
    for (int c = 0; c < nch; ++c) {
        if (c + 1 < nch) issue(c + 1);
        else CP_COMMIT();                 // keep group count uniform
        CP_WAIT1();                       // chunk c resident
        __syncthreads();

        const char* A = smem + (c & 1) * STAGE_BYTES;
        const char* B = A + STAGE_A_BYTES;

        #pragma unroll
        for (int kk = 0; kk < 8; ++kk) {
            uint32_t afl[4], afh[4];
            #pragma unroll
            for (int kh = 0; kh < 2; ++kh) {
                #pragma unroll
                for (int hr = 0; hr < 2; ++hr) {
                    const int2 v = *(const int2*)(A + ((wr * 16 + g + hr * 8) * SA_STRIDE
                                                      + kk * 16 + 2 * t + kh * 8) * 4);
                    const int idx = hr + 2 * kh;
                    afl[idx] = (((uint32_t)v.x << 4) & 0xF0u)
                             | (((uint32_t)v.y << 20) & 0xF00000u) | 0x54005400u;
                    afh[idx] = ((uint32_t)v.x & 0xF0u)
                             | (((uint32_t)v.y << 16) & 0xF00000u) | 0x54005400u;
                }
            }
            #pragma unroll
            for (int nf = 0; nf < 4; ++nf) {
                const int n = wc * 32 + nf * 8 + g;
                uint32_t bf[2];
                bf[0] = *(const uint32_t*)(B + (n * SB_STRIDE + kk * 16 + 2 * t) * 2);
                bf[1] = *(const uint32_t*)(B + (n * SB_STRIDE + kk * 16 + 2 * t + 8) * 2);
                mma16816(accL[nf], afl, bf);
                mma16816(accH[nf], afh, bf);
            }
        }
        __syncthreads();
    }

    // ---- epilogue: transpose through smem, then coalesced float4 stores ----
    float* sm = (float*)smem;                  // [64 b][132] (pad 4) = 33792B
    #pragma unroll
    for (int nf = 0; nf < 4; ++nf)
        #pragma unroll
        for (int q = 0; q < 4; ++q) {
            const int mrow = wr * 16 + g + (q >> 1) * 8;              // 0..63
            const int b    = wc * 32 + nf * 8 + 2 * t + (q & 1);      // 0..63
            sm[b * 132 + mrow]      = accL[nf][q];                    // low nibble
            sm[b * 132 + 64 + mrow] = accH[nf][q];                    // high nibble
        }
    __syncthreads();
    #pragma unroll
    for (int j = 0; j < 8; ++j) {
        const int i = tid + j * 256;           // 2048 float4
        const int b  = i >> 5;
        const int mv = (i & 31) * 4;
        const float4 v = *(const float4*)(sm + b * 132 + mv);
        const long oc = (mv < 64) ? (long)(p0 + mv) : (long)(PROWS + p0 + mv - 64);
        *(float4*)(g_partial + (((long)(slot * BATCH + b)) << 13) + oc) = v;
    }
}

// ---------------------------------------------------------------------------
// Kernel 3: sum the 5 k-slots + affine epilogue (vectorized float4 over oc)
//   out[b,oc] = delta[oc] * (dot' - (zp[oc]+64)*S_h[b]) + bias[oc]
// ---------------------------------------------------------------------------
__global__ void reduce_kernel(const float* __restrict__ delta,
                              const float* __restrict__ zp,
                              const float* __restrict__ bias,
                              float* __restrict__ out) {
    const int idx4 = (blockIdx.x * 256 + threadIdx.x) * 4;  // b*8192 + oc
    const int b  = idx4 >> 13;
    const int oc = idx4 & (OC - 1);
    float4 dot = make_float4(0.f, 0.f, 0.f, 0.f);
    #pragma unroll
    for (int s = 0; s < NSLOT; ++s) {
        const float4 p = *(const float4*)(g_partial + (long)(s * BATCH + b) * OC + oc);
        dot.x += p.x; dot.y += p.y; dot.z += p.z; dot.w += p.w;
    }
    float S = 0.f;
    #pragma unroll
    for (int j = 0; j < 8; ++j) S += g_Spart[b * 8 + j];
    const float4 d  = *(const float4*)(delta + oc);
    const float4 z  = *(const float4*)(zp + oc);
    const float4 bi = *(const float4*)(bias + oc);
    float4 o;
    o.x = d.x * (dot.x - (z.x + 64.f) * S) + bi.x;
    o.y = d.y * (dot.y - (z.y + 64.f) * S) + bi.y;
    o.z = d.z * (dot.z - (z.z + 64.f) * S) + bi.z;
    o.w = d.w * (dot.w - (z.w + 64.f) * S) + bi.w;
    *(float4*)(out + idx4) = o;
}

// ---------------------------------------------------------------------------
// Launch
// ---------------------------------------------------------------------------
extern "C" void kernel_launch(void* const* d_in, const int* in_sizes, int n_in,
                              void* d_out, int out_size) {
    const float* x      = (const float*)d_in[0];
    const int*   packed = (const int*)d_in[1];
    const float* delta  = (const float*)d_in[2];
    const float* zp     = (const float*)d_in[3];
    const float* bias   = (const float*)d_in[4];
    float* out = (float*)d_out;

    cudaFuncSetAttribute(gemm_kernel, cudaFuncAttributeMaxDynamicSharedMemorySize, SMEM_TOTAL);

    prep_kernel<<<512, 256>>>(x);
    gemm_kernel<<<296, 256, SMEM_TOTAL>>>(packed);
    reduce_kernel<<<(BATCH * OC) / 1024, 256>>>(delta, zp, bias, out);
}